// round 1
// baseline (speedup 1.0000x reference)
#include <cuda_runtime.h>
#include <cuda_bf16.h>
#include <math.h>

#define Nn 50000
#define Ee 800000
#define Pp 2
#define Hh 4
#define Ff 32
#define HF 128
#define INF 128

// ---- scratch (device globals; allocation-free) ----
__device__ float g_feat[(size_t)Pp * Nn * HF];   // 51.2 MB
__device__ float g_el[(size_t)Pp * Nn * Hh];
__device__ float g_er[(size_t)Pp * Nn * Hh];
__device__ float g_den[(size_t)Pp * Nn * Hh];
__device__ float g_ex[(size_t)Pp * Ee * Hh];     // 25.6 MB
__device__ float g_out[(size_t)Pp * Nn * HF];    // 51.2 MB
__device__ float g_wsum[Pp];

// ============================================================
// K1: feat = h @ W_p ; el = <feat, al>, er = <feat, ar>
// warp handles 4 nodes, lane handles 4 consecutive cols.
// ============================================================
__global__ void feat_kernel(const float* __restrict__ h,
                            const float* __restrict__ fc_w,
                            const float* __restrict__ attn_l,
                            const float* __restrict__ attn_r) {
    int p = blockIdx.y;
    const float4* W4 = (const float4*)(fc_w + (size_t)p * INF * HF);
    int warpId = threadIdx.x >> 5;
    int lane = threadIdx.x & 31;
    int gw = blockIdx.x * 8 + warpId;
    int n0 = gw * 4;
    if (n0 >= Nn) return;

    int na = min(n0 + 0, Nn - 1);
    int nb = min(n0 + 1, Nn - 1);
    int nc = min(n0 + 2, Nn - 1);
    int nd = min(n0 + 3, Nn - 1);
    const float* ha = h + (size_t)na * INF;
    const float* hb = h + (size_t)nb * INF;
    const float* hc = h + (size_t)nc * INF;
    const float* hd = h + (size_t)nd * INF;

    float4 acc0 = {0,0,0,0}, acc1 = {0,0,0,0}, acc2 = {0,0,0,0}, acc3 = {0,0,0,0};
    #pragma unroll 4
    for (int k = 0; k < INF; k++) {
        float4 wv = W4[k * 32 + lane];
        float h0 = __ldg(ha + k), h1 = __ldg(hb + k), h2 = __ldg(hc + k), h3 = __ldg(hd + k);
        acc0.x += h0 * wv.x; acc0.y += h0 * wv.y; acc0.z += h0 * wv.z; acc0.w += h0 * wv.w;
        acc1.x += h1 * wv.x; acc1.y += h1 * wv.y; acc1.z += h1 * wv.z; acc1.w += h1 * wv.w;
        acc2.x += h2 * wv.x; acc2.y += h2 * wv.y; acc2.z += h2 * wv.z; acc2.w += h2 * wv.w;
        acc3.x += h3 * wv.x; acc3.y += h3 * wv.y; acc3.z += h3 * wv.z; acc3.w += h3 * wv.w;
    }

    float4* feat4 = (float4*)(g_feat + (size_t)p * Nn * HF);
    if (n0 + 0 < Nn) feat4[(size_t)(n0 + 0) * 32 + lane] = acc0;
    if (n0 + 1 < Nn) feat4[(size_t)(n0 + 1) * 32 + lane] = acc1;
    if (n0 + 2 < Nn) feat4[(size_t)(n0 + 2) * 32 + lane] = acc2;
    if (n0 + 3 < Nn) feat4[(size_t)(n0 + 3) * 32 + lane] = acc3;

    // attn dots: head = lane>>3, float4 of al/ar at index 'lane'
    float4 al4 = ((const float4*)(attn_l + (size_t)p * HF))[lane];
    float4 ar4 = ((const float4*)(attn_r + (size_t)p * HF))[lane];
    int head = lane >> 3;

    float4 accs[4] = {acc0, acc1, acc2, acc3};
    #pragma unroll
    for (int j = 0; j < 4; j++) {
        float pl = accs[j].x * al4.x + accs[j].y * al4.y + accs[j].z * al4.z + accs[j].w * al4.w;
        float pr = accs[j].x * ar4.x + accs[j].y * ar4.y + accs[j].z * ar4.z + accs[j].w * ar4.w;
        #pragma unroll
        for (int off = 4; off >= 1; off >>= 1) {
            pl += __shfl_xor_sync(0xffffffffu, pl, off);
            pr += __shfl_xor_sync(0xffffffffu, pr, off);
        }
        int n = n0 + j;
        if ((lane & 7) == 0 && n < Nn) {
            g_el[((size_t)p * Nn + n) * Hh + head] = pl;
            g_er[((size_t)p * Nn + n) * Hh + head] = pr;
        }
    }
}

// ============================================================
// K2: edge logits -> exp (no max subtraction; logits are tiny),
// atomicAdd into denominator per (dst, head)
// ============================================================
__global__ void edge_exp_kernel(const int* __restrict__ src,
                                const int* __restrict__ dst) {
    int p = blockIdx.y;
    int e = blockIdx.x * 256 + threadIdx.x;
    if (e >= Ee) return;
    int s = src[(size_t)p * Ee + e];
    int d = dst[(size_t)p * Ee + e];
    float4 a = ((const float4*)g_el)[(size_t)p * Nn + s];
    float4 b = ((const float4*)g_er)[(size_t)p * Nn + d];
    float4 exv;
    float v;
    v = a.x + b.x; v = v > 0.f ? v : 0.2f * v; exv.x = __expf(v);
    v = a.y + b.y; v = v > 0.f ? v : 0.2f * v; exv.y = __expf(v);
    v = a.z + b.z; v = v > 0.f ? v : 0.2f * v; exv.z = __expf(v);
    v = a.w + b.w; v = v > 0.f ? v : 0.2f * v; exv.w = __expf(v);
    float* denp = g_den + ((size_t)p * Nn + d) * Hh;
    atomicAdd(denp + 0, exv.x);
    atomicAdd(denp + 1, exv.y);
    atomicAdd(denp + 2, exv.z);
    atomicAdd(denp + 3, exv.w);
    ((float4*)g_ex)[(size_t)p * Ee + e] = exv;
}

// K3: den -> 1/max(den, 1e-9)
__global__ void invden_kernel() {
    size_t i = (size_t)blockIdx.x * 256 + threadIdx.x;
    if (i >= (size_t)Pp * Nn * Hh) return;
    g_den[i] = 1.0f / fmaxf(g_den[i], 1e-9f);
}

// ============================================================
// K4: aggregate: out[d] += feat[s] * alpha  (warp per edge)
// ============================================================
__global__ void aggregate_kernel(const int* __restrict__ src,
                                 const int* __restrict__ dst) {
    int p = blockIdx.y;
    int e = blockIdx.x * 8 + (threadIdx.x >> 5);
    if (e >= Ee) return;
    int lane = threadIdx.x & 31;
    int s = src[(size_t)p * Ee + e];
    int d = dst[(size_t)p * Ee + e];
    int head = lane >> 3;
    float alpha = g_ex[((size_t)p * Ee + e) * Hh + head] *
                  g_den[((size_t)p * Nn + d) * Hh + head];
    float4 f = ((const float4*)g_feat)[((size_t)p * Nn + s) * 32 + lane];
    float* o = g_out + ((size_t)p * Nn + d) * HF + lane * 4;
    atomicAdd(o + 0, f.x * alpha);
    atomicAdd(o + 1, f.y * alpha);
    atomicAdd(o + 2, f.z * alpha);
    atomicAdd(o + 3, f.w * alpha);
}

// ============================================================
// K5: semantic attention scores:
// wsum[p] = sum_n tanh(z_p[n] @ W1 + b1) @ w2, z = elu(out + bias)
// block: 256 thr = 8 warps x 4 nodes = 32 nodes; z in smem w/ fused ELU
// ============================================================
__global__ void sem_kernel(const float* __restrict__ bias,
                           const float* __restrict__ sem_w1,
                           const float* __restrict__ sem_b1,
                           const float* __restrict__ sem_w2) {
    __shared__ float z_sh[32 * HF];
    int p = blockIdx.y;
    int base = blockIdx.x * 32;

    for (int i = threadIdx.x; i < 32 * HF; i += 256) {
        int node = base + (i >> 7);
        int c = i & 127;
        float z = 0.f;
        if (node < Nn) {
            float raw = g_out[((size_t)p * Nn + node) * HF + c] + bias[(size_t)p * HF + c];
            z = raw > 0.f ? raw : (__expf(raw) - 1.0f);
        }
        z_sh[i] = z;
    }
    __syncthreads();

    int warpId = threadIdx.x >> 5;
    int lane = threadIdx.x & 31;
    const float4* W14 = (const float4*)sem_w1;

    float4 acc0 = {0,0,0,0}, acc1 = {0,0,0,0}, acc2 = {0,0,0,0}, acc3 = {0,0,0,0};
    #pragma unroll 4
    for (int k = 0; k < HF; k++) {
        float4 wv = W14[k * 32 + lane];
        float z0 = z_sh[(warpId * 4 + 0) * HF + k];
        float z1 = z_sh[(warpId * 4 + 1) * HF + k];
        float z2 = z_sh[(warpId * 4 + 2) * HF + k];
        float z3 = z_sh[(warpId * 4 + 3) * HF + k];
        acc0.x += z0 * wv.x; acc0.y += z0 * wv.y; acc0.z += z0 * wv.z; acc0.w += z0 * wv.w;
        acc1.x += z1 * wv.x; acc1.y += z1 * wv.y; acc1.z += z1 * wv.z; acc1.w += z1 * wv.w;
        acc2.x += z2 * wv.x; acc2.y += z2 * wv.y; acc2.z += z2 * wv.z; acc2.w += z2 * wv.w;
        acc3.x += z3 * wv.x; acc3.y += z3 * wv.y; acc3.z += z3 * wv.z; acc3.w += z3 * wv.w;
    }

    float4 b14 = ((const float4*)sem_b1)[lane];
    float4 w24 = ((const float4*)sem_w2)[lane];

    float4 accs[4] = {acc0, acc1, acc2, acc3};
    float total = 0.f;
    #pragma unroll
    for (int j = 0; j < 4; j++) {
        float cj = tanhf(accs[j].x + b14.x) * w24.x
                 + tanhf(accs[j].y + b14.y) * w24.y
                 + tanhf(accs[j].z + b14.z) * w24.z
                 + tanhf(accs[j].w + b14.w) * w24.w;
        #pragma unroll
        for (int off = 16; off >= 1; off >>= 1)
            cj += __shfl_xor_sync(0xffffffffu, cj, off);
        int node = base + warpId * 4 + j;
        if (node < Nn) total += cj;
    }
    if (lane == 0 && total != 0.f) atomicAdd(&g_wsum[p], total);
    else if (lane == 0) atomicAdd(&g_wsum[p], total);  // keep deterministic path simple
}

// ============================================================
// K6: beta = softmax(wsum/N); out = b0*elu(o0+bias0)+b1*elu(o1+bias1)
// ============================================================
__global__ void final_kernel(const float* __restrict__ bias,
                             float* __restrict__ out) {
    size_t i = (size_t)blockIdx.x * 256 + threadIdx.x;
    if (i >= (size_t)Nn * 32) return;
    float w0 = g_wsum[0] * (1.0f / Nn);
    float w1 = g_wsum[1] * (1.0f / Nn);
    float m = fmaxf(w0, w1);
    float e0 = __expf(w0 - m), e1 = __expf(w1 - m);
    float inv = 1.0f / (e0 + e1);
    float b0 = e0 * inv, b1 = e1 * inv;

    int c4 = (int)(i & 31);
    float4 r0 = ((const float4*)g_out)[i];
    float4 r1 = ((const float4*)g_out)[(size_t)Nn * 32 + i];
    float4 bi0 = ((const float4*)bias)[c4];
    float4 bi1 = ((const float4*)bias)[32 + c4];

    float4 res;
    float v;
    v = r0.x + bi0.x; v = v > 0.f ? v : (__expf(v) - 1.f); res.x = b0 * v;
    v = r0.y + bi0.y; v = v > 0.f ? v : (__expf(v) - 1.f); res.y = b0 * v;
    v = r0.z + bi0.z; v = v > 0.f ? v : (__expf(v) - 1.f); res.z = b0 * v;
    v = r0.w + bi0.w; v = v > 0.f ? v : (__expf(v) - 1.f); res.w = b0 * v;
    v = r1.x + bi1.x; v = v > 0.f ? v : (__expf(v) - 1.f); res.x += b1 * v;
    v = r1.y + bi1.y; v = v > 0.f ? v : (__expf(v) - 1.f); res.y += b1 * v;
    v = r1.z + bi1.z; v = v > 0.f ? v : (__expf(v) - 1.f); res.z += b1 * v;
    v = r1.w + bi1.w; v = v > 0.f ? v : (__expf(v) - 1.f); res.w += b1 * v;

    ((float4*)out)[i] = res;
}

extern "C" void kernel_launch(void* const* d_in, const int* in_sizes, int n_in,
                              void* d_out, int out_size) {
    const float* h      = (const float*)d_in[0];
    const int*   src    = (const int*)  d_in[1];
    const int*   dst    = (const int*)  d_in[2];
    const float* fc_w   = (const float*)d_in[3];
    const float* attn_l = (const float*)d_in[4];
    const float* attn_r = (const float*)d_in[5];
    const float* bias   = (const float*)d_in[6];
    const float* sem_w1 = (const float*)d_in[7];
    const float* sem_b1 = (const float*)d_in[8];
    const float* sem_w2 = (const float*)d_in[9];
    float* out = (float*)d_out;

    void *p_den, *p_out, *p_wsum;
    cudaGetSymbolAddress(&p_den, g_den);
    cudaGetSymbolAddress(&p_out, g_out);
    cudaGetSymbolAddress(&p_wsum, g_wsum);
    cudaMemsetAsync(p_den, 0, sizeof(float) * (size_t)Pp * Nn * Hh);
    cudaMemsetAsync(p_out, 0, sizeof(float) * (size_t)Pp * Nn * HF);
    cudaMemsetAsync(p_wsum, 0, sizeof(float) * Pp);

    // K1: features + attn dots (warps = ceil(N/4)=12500 -> 1563 blocks of 8 warps)
    dim3 gFeat((Nn / 4 + 7) / 8, Pp);
    feat_kernel<<<gFeat, 256>>>(h, fc_w, attn_l, attn_r);

    // K2: edge exp + denominator
    dim3 gEdge((Ee + 255) / 256, Pp);
    edge_exp_kernel<<<gEdge, 256>>>(src, dst);

    // K3: reciprocal denominators
    invden_kernel<<<((size_t)Pp * Nn * Hh + 255) / 256, 256>>>();

    // K4: aggregation (warp per edge)
    dim3 gAgg(Ee / 8, Pp);
    aggregate_kernel<<<gAgg, 256>>>(src, dst);

    // K5: semantic attention scores
    dim3 gSem((Nn + 31) / 32, Pp);
    sem_kernel<<<gSem, 256>>>(bias, sem_w1, sem_b1, sem_w2);

    // K6: combine
    final_kernel<<<((size_t)Nn * 32 + 255) / 256, 256>>>(bias, out);
}

// round 2
// speedup vs baseline: 1.9563x; 1.9563x over previous
#include <cuda_runtime.h>
#include <cuda_bf16.h>
#include <math.h>

#define Nn 50000
#define Ee 800000
#define Pp 2
#define Hh 4
#define Ff 32
#define HF 128
#define INF 128
#define TOT (Pp * Nn)          // 100000 destination slots
#define SCAN_B 98              // ceil(TOT/1024)

// ---- scratch (device globals; allocation-free) ----
__device__ float g_feat[(size_t)Pp * Nn * HF];   // 51.2 MB
__device__ float g_el[(size_t)Pp * Nn * Hh];
__device__ float g_er[(size_t)Pp * Nn * Hh];
__device__ float g_out[(size_t)Pp * Nn * HF];    // 51.2 MB
__device__ float g_wsum[Pp];
__device__ int   g_deg[TOT];
__device__ int   g_off[TOT];
__device__ int   g_cur[TOT];
__device__ int   g_bsum[SCAN_B];
__device__ int   g_bscan[SCAN_B];
__device__ int   g_csr_src[(size_t)Pp * Ee];     // 6.4 MB

// ============================================================
// K1: feat = h @ W_p ; el = <feat, al>, er = <feat, ar>
// ============================================================
__global__ void feat_kernel(const float* __restrict__ h,
                            const float* __restrict__ fc_w,
                            const float* __restrict__ attn_l,
                            const float* __restrict__ attn_r) {
    int p = blockIdx.y;
    const float4* W4 = (const float4*)(fc_w + (size_t)p * INF * HF);
    int warpId = threadIdx.x >> 5;
    int lane = threadIdx.x & 31;
    int gw = blockIdx.x * 8 + warpId;
    int n0 = gw * 4;
    if (n0 >= Nn) return;

    int na = min(n0 + 0, Nn - 1);
    int nb = min(n0 + 1, Nn - 1);
    int nc = min(n0 + 2, Nn - 1);
    int nd = min(n0 + 3, Nn - 1);
    const float* ha = h + (size_t)na * INF;
    const float* hb = h + (size_t)nb * INF;
    const float* hc = h + (size_t)nc * INF;
    const float* hd = h + (size_t)nd * INF;

    float4 acc0 = {0,0,0,0}, acc1 = {0,0,0,0}, acc2 = {0,0,0,0}, acc3 = {0,0,0,0};
    #pragma unroll 4
    for (int k = 0; k < INF; k++) {
        float4 wv = W4[k * 32 + lane];
        float h0 = __ldg(ha + k), h1 = __ldg(hb + k), h2 = __ldg(hc + k), h3 = __ldg(hd + k);
        acc0.x += h0 * wv.x; acc0.y += h0 * wv.y; acc0.z += h0 * wv.z; acc0.w += h0 * wv.w;
        acc1.x += h1 * wv.x; acc1.y += h1 * wv.y; acc1.z += h1 * wv.z; acc1.w += h1 * wv.w;
        acc2.x += h2 * wv.x; acc2.y += h2 * wv.y; acc2.z += h2 * wv.z; acc2.w += h2 * wv.w;
        acc3.x += h3 * wv.x; acc3.y += h3 * wv.y; acc3.z += h3 * wv.z; acc3.w += h3 * wv.w;
    }

    float4* feat4 = (float4*)(g_feat + (size_t)p * Nn * HF);
    if (n0 + 0 < Nn) feat4[(size_t)(n0 + 0) * 32 + lane] = acc0;
    if (n0 + 1 < Nn) feat4[(size_t)(n0 + 1) * 32 + lane] = acc1;
    if (n0 + 2 < Nn) feat4[(size_t)(n0 + 2) * 32 + lane] = acc2;
    if (n0 + 3 < Nn) feat4[(size_t)(n0 + 3) * 32 + lane] = acc3;

    float4 al4 = ((const float4*)(attn_l + (size_t)p * HF))[lane];
    float4 ar4 = ((const float4*)(attn_r + (size_t)p * HF))[lane];
    int head = lane >> 3;

    float4 accs[4] = {acc0, acc1, acc2, acc3};
    #pragma unroll
    for (int j = 0; j < 4; j++) {
        float pl = accs[j].x * al4.x + accs[j].y * al4.y + accs[j].z * al4.z + accs[j].w * al4.w;
        float pr = accs[j].x * ar4.x + accs[j].y * ar4.y + accs[j].z * ar4.z + accs[j].w * ar4.w;
        #pragma unroll
        for (int off = 4; off >= 1; off >>= 1) {
            pl += __shfl_xor_sync(0xffffffffu, pl, off);
            pr += __shfl_xor_sync(0xffffffffu, pr, off);
        }
        int n = n0 + j;
        if ((lane & 7) == 0 && n < Nn) {
            g_el[((size_t)p * Nn + n) * Hh + head] = pl;
            g_er[((size_t)p * Nn + n) * Hh + head] = pr;
        }
    }
}

// ============================================================
// CSR build: histogram -> scan -> scatter
// ============================================================
__global__ void hist_kernel(const int* __restrict__ dst) {
    int p = blockIdx.y;
    int e = blockIdx.x * 256 + threadIdx.x;
    if (e >= Ee) return;
    atomicAdd(&g_deg[p * Nn + dst[(size_t)p * Ee + e]], 1);
}

// block-level exclusive scan (1024/block)
__global__ void scan1_kernel() {
    __shared__ int wsum[32];
    int tid = threadIdx.x, lane = tid & 31, wid = tid >> 5;
    int i = blockIdx.x * 1024 + tid;
    int v = (i < TOT) ? g_deg[i] : 0;
    int x = v;
    #pragma unroll
    for (int o = 1; o < 32; o <<= 1) {
        int y = __shfl_up_sync(0xffffffffu, x, o);
        if (lane >= o) x += y;
    }
    if (lane == 31) wsum[wid] = x;
    __syncthreads();
    if (wid == 0) {
        int s = wsum[lane];
        #pragma unroll
        for (int o = 1; o < 32; o <<= 1) {
            int y = __shfl_up_sync(0xffffffffu, s, o);
            if (lane >= o) s += y;
        }
        wsum[lane] = s;
    }
    __syncthreads();
    int woff = (wid == 0) ? 0 : wsum[wid - 1];
    if (i < TOT) g_off[i] = woff + x - v;
    if (tid == 1023) g_bsum[blockIdx.x] = wsum[31];
}

// scan of the SCAN_B block sums (1 warp)
__global__ void scan2_kernel() {
    int lane = threadIdx.x;
    int v[4];
    int s = 0;
    #pragma unroll
    for (int j = 0; j < 4; j++) {
        int idx = lane * 4 + j;
        int t = (idx < SCAN_B) ? g_bsum[idx] : 0;
        v[j] = s;          // prefix within lane
        s += t;
    }
    int x = s;
    #pragma unroll
    for (int o = 1; o < 32; o <<= 1) {
        int y = __shfl_up_sync(0xffffffffu, x, o);
        if (lane >= o) x += y;
    }
    int excl = x - s;
    #pragma unroll
    for (int j = 0; j < 4; j++) {
        int idx = lane * 4 + j;
        if (idx < SCAN_B) g_bscan[idx] = excl + v[j];
    }
}

__global__ void scan3_kernel() {
    int i = blockIdx.x * 1024 + threadIdx.x;
    if (i >= TOT) return;
    int o = g_off[i] + g_bscan[blockIdx.x];
    g_off[i] = o;
    g_cur[i] = o;
}

__global__ void scatter_kernel(const int* __restrict__ src,
                               const int* __restrict__ dst) {
    int p = blockIdx.y;
    int e = blockIdx.x * 256 + threadIdx.x;
    if (e >= Ee) return;
    size_t idx = (size_t)p * Ee + e;
    int d = dst[idx];
    int pos = atomicAdd(&g_cur[p * Nn + d], 1);
    g_csr_src[pos] = src[idx];
}

// ============================================================
// K4: CSR aggregation — warp per destination node.
// Recomputes edge softmax weights inline from el/er; register
// accumulation; single normalized store (no atomics, no g_ex).
// ============================================================
__global__ void agg_kernel() {
    int w = blockIdx.x * 8 + (threadIdx.x >> 5);
    if (w >= TOT) return;
    int lane = threadIdx.x & 31;
    int p = (w >= Nn) ? 1 : 0;
    size_t pbase = (size_t)p * Nn;

    int beg = g_off[w];
    int deg = g_deg[w];
    int head = lane >> 3;
    float erd = g_er[(size_t)w * Hh + head];

    const float4* feat4 = (const float4*)g_feat;
    float4 acc0 = {0,0,0,0}, acc1 = {0,0,0,0};
    float den0 = 0.f, den1 = 0.f;

    for (int j = 0; j < deg; j += 32) {
        int cnt = min(32, deg - j);
        int s = (lane < cnt) ? g_csr_src[beg + j + lane] : 0;
        int k = 0;
        for (; k + 1 < cnt; k += 2) {
            int sa = __shfl_sync(0xffffffffu, s, k);
            int sb = __shfl_sync(0xffffffffu, s, k + 1);
            float ela = g_el[(pbase + sa) * Hh + head];
            float elb = g_el[(pbase + sb) * Hh + head];
            float4 fa = feat4[(pbase + sa) * 32 + lane];
            float4 fb = feat4[(pbase + sb) * 32 + lane];
            float va = ela + erd; va = va > 0.f ? va : 0.2f * va;
            float vb = elb + erd; vb = vb > 0.f ? vb : 0.2f * vb;
            float wa = __expf(va);
            float wb = __expf(vb);
            acc0.x += wa * fa.x; acc0.y += wa * fa.y; acc0.z += wa * fa.z; acc0.w += wa * fa.w;
            acc1.x += wb * fb.x; acc1.y += wb * fb.y; acc1.z += wb * fb.z; acc1.w += wb * fb.w;
            den0 += wa; den1 += wb;
        }
        if (k < cnt) {
            int sa = __shfl_sync(0xffffffffu, s, k);
            float ela = g_el[(pbase + sa) * Hh + head];
            float4 fa = feat4[(pbase + sa) * 32 + lane];
            float va = ela + erd; va = va > 0.f ? va : 0.2f * va;
            float wa = __expf(va);
            acc0.x += wa * fa.x; acc0.y += wa * fa.y; acc0.z += wa * fa.z; acc0.w += wa * fa.w;
            den0 += wa;
        }
    }
    float inv = 1.0f / fmaxf(den0 + den1, 1e-9f);
    float4 r;
    r.x = (acc0.x + acc1.x) * inv;
    r.y = (acc0.y + acc1.y) * inv;
    r.z = (acc0.z + acc1.z) * inv;
    r.w = (acc0.w + acc1.w) * inv;
    ((float4*)g_out)[(size_t)w * 32 + lane] = r;
}

// ============================================================
// K5: semantic attention scores
// ============================================================
__global__ void sem_kernel(const float* __restrict__ bias,
                           const float* __restrict__ sem_w1,
                           const float* __restrict__ sem_b1,
                           const float* __restrict__ sem_w2) {
    __shared__ float z_sh[32 * HF];
    int p = blockIdx.y;
    int base = blockIdx.x * 32;

    for (int i = threadIdx.x; i < 32 * HF; i += 256) {
        int node = base + (i >> 7);
        int c = i & 127;
        float z = 0.f;
        if (node < Nn) {
            float raw = g_out[((size_t)p * Nn + node) * HF + c] + bias[(size_t)p * HF + c];
            z = raw > 0.f ? raw : (__expf(raw) - 1.0f);
        }
        z_sh[i] = z;
    }
    __syncthreads();

    int warpId = threadIdx.x >> 5;
    int lane = threadIdx.x & 31;
    const float4* W14 = (const float4*)sem_w1;

    float4 acc0 = {0,0,0,0}, acc1 = {0,0,0,0}, acc2 = {0,0,0,0}, acc3 = {0,0,0,0};
    #pragma unroll 4
    for (int k = 0; k < HF; k++) {
        float4 wv = W14[k * 32 + lane];
        float z0 = z_sh[(warpId * 4 + 0) * HF + k];
        float z1 = z_sh[(warpId * 4 + 1) * HF + k];
        float z2 = z_sh[(warpId * 4 + 2) * HF + k];
        float z3 = z_sh[(warpId * 4 + 3) * HF + k];
        acc0.x += z0 * wv.x; acc0.y += z0 * wv.y; acc0.z += z0 * wv.z; acc0.w += z0 * wv.w;
        acc1.x += z1 * wv.x; acc1.y += z1 * wv.y; acc1.z += z1 * wv.z; acc1.w += z1 * wv.w;
        acc2.x += z2 * wv.x; acc2.y += z2 * wv.y; acc2.z += z2 * wv.z; acc2.w += z2 * wv.w;
        acc3.x += z3 * wv.x; acc3.y += z3 * wv.y; acc3.z += z3 * wv.z; acc3.w += z3 * wv.w;
    }

    float4 b14 = ((const float4*)sem_b1)[lane];
    float4 w24 = ((const float4*)sem_w2)[lane];

    float4 accs[4] = {acc0, acc1, acc2, acc3};
    float total = 0.f;
    #pragma unroll
    for (int j = 0; j < 4; j++) {
        float cj = tanhf(accs[j].x + b14.x) * w24.x
                 + tanhf(accs[j].y + b14.y) * w24.y
                 + tanhf(accs[j].z + b14.z) * w24.z
                 + tanhf(accs[j].w + b14.w) * w24.w;
        #pragma unroll
        for (int off = 16; off >= 1; off >>= 1)
            cj += __shfl_xor_sync(0xffffffffu, cj, off);
        int node = base + warpId * 4 + j;
        if (node < Nn) total += cj;
    }
    if (lane == 0) atomicAdd(&g_wsum[p], total);
}

// ============================================================
// K6: combine with semantic softmax
// ============================================================
__global__ void final_kernel(const float* __restrict__ bias,
                             float* __restrict__ out) {
    size_t i = (size_t)blockIdx.x * 256 + threadIdx.x;
    if (i >= (size_t)Nn * 32) return;
    float w0 = g_wsum[0] * (1.0f / Nn);
    float w1 = g_wsum[1] * (1.0f / Nn);
    float m = fmaxf(w0, w1);
    float e0 = __expf(w0 - m), e1 = __expf(w1 - m);
    float inv = 1.0f / (e0 + e1);
    float b0 = e0 * inv, b1 = e1 * inv;

    int c4 = (int)(i & 31);
    float4 r0 = ((const float4*)g_out)[i];
    float4 r1 = ((const float4*)g_out)[(size_t)Nn * 32 + i];
    float4 bi0 = ((const float4*)bias)[c4];
    float4 bi1 = ((const float4*)bias)[32 + c4];

    float4 res;
    float v;
    v = r0.x + bi0.x; v = v > 0.f ? v : (__expf(v) - 1.f); res.x = b0 * v;
    v = r0.y + bi0.y; v = v > 0.f ? v : (__expf(v) - 1.f); res.y = b0 * v;
    v = r0.z + bi0.z; v = v > 0.f ? v : (__expf(v) - 1.f); res.z = b0 * v;
    v = r0.w + bi0.w; v = v > 0.f ? v : (__expf(v) - 1.f); res.w = b0 * v;
    v = r1.x + bi1.x; v = v > 0.f ? v : (__expf(v) - 1.f); res.x += b1 * v;
    v = r1.y + bi1.y; v = v > 0.f ? v : (__expf(v) - 1.f); res.y += b1 * v;
    v = r1.z + bi1.z; v = v > 0.f ? v : (__expf(v) - 1.f); res.z += b1 * v;
    v = r1.w + bi1.w; v = v > 0.f ? v : (__expf(v) - 1.f); res.w += b1 * v;

    ((float4*)out)[i] = res;
}

extern "C" void kernel_launch(void* const* d_in, const int* in_sizes, int n_in,
                              void* d_out, int out_size) {
    const float* h      = (const float*)d_in[0];
    const int*   src    = (const int*)  d_in[1];
    const int*   dst    = (const int*)  d_in[2];
    const float* fc_w   = (const float*)d_in[3];
    const float* attn_l = (const float*)d_in[4];
    const float* attn_r = (const float*)d_in[5];
    const float* bias   = (const float*)d_in[6];
    const float* sem_w1 = (const float*)d_in[7];
    const float* sem_b1 = (const float*)d_in[8];
    const float* sem_w2 = (const float*)d_in[9];
    float* out = (float*)d_out;

    void *p_deg, *p_wsum;
    cudaGetSymbolAddress(&p_deg, g_deg);
    cudaGetSymbolAddress(&p_wsum, g_wsum);
    cudaMemsetAsync(p_deg, 0, sizeof(int) * TOT);
    cudaMemsetAsync(p_wsum, 0, sizeof(float) * Pp);

    // features + attn dots
    dim3 gFeat((Nn / 4 + 7) / 8, Pp);
    feat_kernel<<<gFeat, 256>>>(h, fc_w, attn_l, attn_r);

    // CSR build
    dim3 gEdge((Ee + 255) / 256, Pp);
    hist_kernel<<<gEdge, 256>>>(dst);
    scan1_kernel<<<SCAN_B, 1024>>>();
    scan2_kernel<<<1, 32>>>();
    scan3_kernel<<<SCAN_B, 1024>>>();
    scatter_kernel<<<gEdge, 256>>>(src, dst);

    // aggregation (warp per dst node)
    agg_kernel<<<(TOT + 7) / 8, 256>>>();

    // semantic attention
    dim3 gSem((Nn + 31) / 32, Pp);
    sem_kernel<<<gSem, 256>>>(bias, sem_w1, sem_b1, sem_w2);

    final_kernel<<<((size_t)Nn * 32 + 255) / 256, 256>>>(bias, out);
}

// round 3
// speedup vs baseline: 2.0881x; 1.0674x over previous
#include <cuda_runtime.h>
#include <cuda_bf16.h>
#include <math.h>

#define Nn 50000
#define Ee 800000
#define Pp 2
#define Hh 4
#define Ff 32
#define HF 128
#define INF 128
#define TOT (Pp * Nn)          // 100000 destination slots
#define SCAN_B 98              // ceil(TOT/1024)

// ---- scratch (device globals; allocation-free) ----
__device__ float g_feat[(size_t)Pp * Nn * HF];   // 51.2 MB
__device__ float g_el[(size_t)Pp * Nn * Hh];
__device__ float g_er[(size_t)Pp * Nn * Hh];
__device__ float g_out[(size_t)Pp * Nn * HF];    // 51.2 MB
__device__ float g_wsum[Pp];
__device__ int   g_deg[TOT];
__device__ int   g_off[TOT];
__device__ int   g_cur[TOT];
__device__ int   g_bsum[SCAN_B];
__device__ int   g_csr_src[(size_t)Pp * Ee];     // 6.4 MB

// ---- packed fp32x2 helpers (Blackwell) ----
__device__ __forceinline__ unsigned long long pack2(float a, float b) {
    unsigned long long r;
    asm("mov.b64 %0, {%1, %2};" : "=l"(r) : "f"(a), "f"(b));
    return r;
}
__device__ __forceinline__ void unpack2(unsigned long long v, float& a, float& b) {
    asm("mov.b64 {%0, %1}, %2;" : "=f"(a), "=f"(b) : "l"(v));
}
__device__ __forceinline__ unsigned long long fma2(unsigned long long a,
                                                   unsigned long long b,
                                                   unsigned long long c) {
    unsigned long long r;
    asm("fma.rn.f32x2 %0, %1, %2, %3;" : "=l"(r) : "l"(a), "l"(b), "l"(c));
    return r;
}

// ============================================================
// K1: feat = h @ W_p ; el = <feat, al>, er = <feat, ar>
// warp = 4 nodes, lane = 4 consecutive cols; packed f32x2 FMA.
// ============================================================
__global__ void feat_kernel(const float* __restrict__ h,
                            const float* __restrict__ fc_w,
                            const float* __restrict__ attn_l,
                            const float* __restrict__ attn_r) {
    int p = blockIdx.y;
    const ulonglong2* W2 = (const ulonglong2*)(fc_w + (size_t)p * INF * HF);
    int warpId = threadIdx.x >> 5;
    int lane = threadIdx.x & 31;
    int gw = blockIdx.x * 8 + warpId;
    int n0 = gw * 4;                    // Nn % 4 == 0
    if (n0 >= Nn) return;

    const float4* h4 = (const float4*)h;
    const float4* ha = h4 + (size_t)(n0 + 0) * 32;
    const float4* hb = h4 + (size_t)(n0 + 1) * 32;
    const float4* hc = h4 + (size_t)(n0 + 2) * 32;
    const float4* hd = h4 + (size_t)(n0 + 3) * 32;

    unsigned long long acc[4][2];
    #pragma unroll
    for (int r = 0; r < 4; r++) { acc[r][0] = 0ull; acc[r][1] = 0ull; }

    for (int k4 = 0; k4 < 32; k4++) {         // 32 chunks of 4 k-steps
        float4 hv0 = __ldg(ha + k4);
        float4 hv1 = __ldg(hb + k4);
        float4 hv2 = __ldg(hc + k4);
        float4 hv3 = __ldg(hd + k4);
        float h0v[4] = {hv0.x, hv0.y, hv0.z, hv0.w};
        float h1v[4] = {hv1.x, hv1.y, hv1.z, hv1.w};
        float h2v[4] = {hv2.x, hv2.y, hv2.z, hv2.w};
        float h3v[4] = {hv3.x, hv3.y, hv3.z, hv3.w};
        #pragma unroll
        for (int kk = 0; kk < 4; kk++) {
            ulonglong2 wv = W2[(size_t)(k4 * 4 + kk) * 32 + lane];
            unsigned long long p0 = pack2(h0v[kk], h0v[kk]);
            unsigned long long p1 = pack2(h1v[kk], h1v[kk]);
            unsigned long long p2 = pack2(h2v[kk], h2v[kk]);
            unsigned long long p3 = pack2(h3v[kk], h3v[kk]);
            acc[0][0] = fma2(p0, wv.x, acc[0][0]); acc[0][1] = fma2(p0, wv.y, acc[0][1]);
            acc[1][0] = fma2(p1, wv.x, acc[1][0]); acc[1][1] = fma2(p1, wv.y, acc[1][1]);
            acc[2][0] = fma2(p2, wv.x, acc[2][0]); acc[2][1] = fma2(p2, wv.y, acc[2][1]);
            acc[3][0] = fma2(p3, wv.x, acc[3][0]); acc[3][1] = fma2(p3, wv.y, acc[3][1]);
        }
    }

    float4 accs[4];
    #pragma unroll
    for (int r = 0; r < 4; r++) {
        unpack2(acc[r][0], accs[r].x, accs[r].y);
        unpack2(acc[r][1], accs[r].z, accs[r].w);
    }

    float4* feat4 = (float4*)(g_feat + (size_t)p * Nn * HF);
    #pragma unroll
    for (int r = 0; r < 4; r++)
        feat4[(size_t)(n0 + r) * 32 + lane] = accs[r];

    float4 al4 = ((const float4*)(attn_l + (size_t)p * HF))[lane];
    float4 ar4 = ((const float4*)(attn_r + (size_t)p * HF))[lane];
    int head = lane >> 3;

    #pragma unroll
    for (int j = 0; j < 4; j++) {
        float pl = accs[j].x * al4.x + accs[j].y * al4.y + accs[j].z * al4.z + accs[j].w * al4.w;
        float pr = accs[j].x * ar4.x + accs[j].y * ar4.y + accs[j].z * ar4.z + accs[j].w * ar4.w;
        #pragma unroll
        for (int off = 4; off >= 1; off >>= 1) {
            pl += __shfl_xor_sync(0xffffffffu, pl, off);
            pr += __shfl_xor_sync(0xffffffffu, pr, off);
        }
        if ((lane & 7) == 0) {
            g_el[((size_t)p * Nn + n0 + j) * Hh + head] = pl;
            g_er[((size_t)p * Nn + n0 + j) * Hh + head] = pr;
        }
    }
}

// ============================================================
// CSR build: histogram -> scan -> scatter
// ============================================================
__global__ void hist_kernel(const int* __restrict__ dst) {
    int p = blockIdx.y;
    int e = blockIdx.x * 256 + threadIdx.x;
    if (e >= Ee) return;
    atomicAdd(&g_deg[p * Nn + __ldg(dst + (size_t)p * Ee + e)], 1);
}

__global__ void scan1_kernel() {
    __shared__ int wsum[32];
    int tid = threadIdx.x, lane = tid & 31, wid = tid >> 5;
    int i = blockIdx.x * 1024 + tid;
    int v = (i < TOT) ? g_deg[i] : 0;
    int x = v;
    #pragma unroll
    for (int o = 1; o < 32; o <<= 1) {
        int y = __shfl_up_sync(0xffffffffu, x, o);
        if (lane >= o) x += y;
    }
    if (lane == 31) wsum[wid] = x;
    __syncthreads();
    if (wid == 0) {
        int s = wsum[lane];
        #pragma unroll
        for (int o = 1; o < 32; o <<= 1) {
            int y = __shfl_up_sync(0xffffffffu, s, o);
            if (lane >= o) s += y;
        }
        wsum[lane] = s;
    }
    __syncthreads();
    int woff = (wid == 0) ? 0 : wsum[wid - 1];
    if (i < TOT) g_off[i] = woff + x - v;
    if (tid == 1023) g_bsum[blockIdx.x] = wsum[31];
}

// fused scan of block sums + add-back (each block redundantly scans 98 ints)
__global__ void scan23_kernel() {
    __shared__ int sh_scan[SCAN_B];
    if (threadIdx.x < 32) {
        int lane = threadIdx.x;
        int v[4];
        int s = 0;
        #pragma unroll
        for (int j = 0; j < 4; j++) {
            int idx = lane * 4 + j;
            int t = (idx < SCAN_B) ? g_bsum[idx] : 0;
            v[j] = s;
            s += t;
        }
        int x = s;
        #pragma unroll
        for (int o = 1; o < 32; o <<= 1) {
            int y = __shfl_up_sync(0xffffffffu, x, o);
            if (lane >= o) x += y;
        }
        int excl = x - s;
        #pragma unroll
        for (int j = 0; j < 4; j++) {
            int idx = lane * 4 + j;
            if (idx < SCAN_B) sh_scan[idx] = excl + v[j];
        }
    }
    __syncthreads();
    int i = blockIdx.x * 1024 + threadIdx.x;
    if (i < TOT) {
        int o = g_off[i] + sh_scan[blockIdx.x];
        g_off[i] = o;
        g_cur[i] = o;
    }
}

__global__ void scatter_kernel(const int* __restrict__ src,
                               const int* __restrict__ dst) {
    int p = blockIdx.y;
    int e = blockIdx.x * 256 + threadIdx.x;
    if (e >= Ee) return;
    size_t idx = (size_t)p * Ee + e;
    int d = __ldg(dst + idx);
    int pos = atomicAdd(&g_cur[p * Nn + d], 1);
    g_csr_src[pos] = __ldg(src + idx);
}

// ============================================================
// K4: CSR aggregation — warp per destination node, unroll 4.
// ============================================================
__global__ void agg_kernel() {
    int w = blockIdx.x * 8 + (threadIdx.x >> 5);
    if (w >= TOT) return;
    int lane = threadIdx.x & 31;
    int p = (w >= Nn) ? 1 : 0;
    size_t pbase = (size_t)p * Nn;

    int beg = g_off[w];
    int deg = g_deg[w];
    int head = lane >> 3;
    float erd = g_er[(size_t)w * Hh + head];

    const ulonglong2* feat2 = (const ulonglong2*)g_feat;
    unsigned long long a00 = 0ull, a01 = 0ull;   // even edges
    unsigned long long a10 = 0ull, a11 = 0ull;   // odd edges
    float den = 0.f;

    for (int j = 0; j < deg; j += 32) {
        int cnt = min(32, deg - j);
        int s = g_csr_src[beg + j + min(lane, cnt - 1)];
        int k = 0;
        for (; k + 4 <= cnt; k += 4) {
            int s0 = __shfl_sync(0xffffffffu, s, k);
            int s1 = __shfl_sync(0xffffffffu, s, k + 1);
            int s2 = __shfl_sync(0xffffffffu, s, k + 2);
            int s3 = __shfl_sync(0xffffffffu, s, k + 3);
            float e0 = g_el[(pbase + s0) * Hh + head];
            float e1 = g_el[(pbase + s1) * Hh + head];
            float e2 = g_el[(pbase + s2) * Hh + head];
            float e3 = g_el[(pbase + s3) * Hh + head];
            ulonglong2 f0 = feat2[(pbase + s0) * 32 + lane];
            ulonglong2 f1 = feat2[(pbase + s1) * 32 + lane];
            ulonglong2 f2 = feat2[(pbase + s2) * 32 + lane];
            ulonglong2 f3 = feat2[(pbase + s3) * 32 + lane];
            float v0 = e0 + erd; v0 = v0 > 0.f ? v0 : 0.2f * v0;
            float v1 = e1 + erd; v1 = v1 > 0.f ? v1 : 0.2f * v1;
            float v2 = e2 + erd; v2 = v2 > 0.f ? v2 : 0.2f * v2;
            float v3 = e3 + erd; v3 = v3 > 0.f ? v3 : 0.2f * v3;
            float w0 = __expf(v0), w1 = __expf(v1), w2 = __expf(v2), w3 = __expf(v3);
            unsigned long long p0 = pack2(w0, w0);
            unsigned long long p1 = pack2(w1, w1);
            unsigned long long p2 = pack2(w2, w2);
            unsigned long long p3 = pack2(w3, w3);
            a00 = fma2(p0, f0.x, a00); a01 = fma2(p0, f0.y, a01);
            a10 = fma2(p1, f1.x, a10); a11 = fma2(p1, f1.y, a11);
            a00 = fma2(p2, f2.x, a00); a01 = fma2(p2, f2.y, a01);
            a10 = fma2(p3, f3.x, a10); a11 = fma2(p3, f3.y, a11);
            den += (w0 + w1) + (w2 + w3);
        }
        for (; k < cnt; k++) {
            int s0 = __shfl_sync(0xffffffffu, s, k);
            float e0 = g_el[(pbase + s0) * Hh + head];
            ulonglong2 f0 = feat2[(pbase + s0) * 32 + lane];
            float v0 = e0 + erd; v0 = v0 > 0.f ? v0 : 0.2f * v0;
            float w0 = __expf(v0);
            unsigned long long p0 = pack2(w0, w0);
            a00 = fma2(p0, f0.x, a00); a01 = fma2(p0, f0.y, a01);
            den += w0;
        }
    }

    float ax0, ay0, az0, aw0, ax1, ay1, az1, aw1;
    unpack2(a00, ax0, ay0); unpack2(a01, az0, aw0);
    unpack2(a10, ax1, ay1); unpack2(a11, az1, aw1);
    float inv = 1.0f / fmaxf(den, 1e-9f);
    float4 r;
    r.x = (ax0 + ax1) * inv;
    r.y = (ay0 + ay1) * inv;
    r.z = (az0 + az1) * inv;
    r.w = (aw0 + aw1) * inv;
    ((float4*)g_out)[(size_t)w * 32 + lane] = r;
}

// ============================================================
// K5: semantic attention scores (packed f32x2 GEMM)
// ============================================================
__global__ void sem_kernel(const float* __restrict__ bias,
                           const float* __restrict__ sem_w1,
                           const float* __restrict__ sem_b1,
                           const float* __restrict__ sem_w2) {
    __shared__ __align__(16) float z_sh[32 * HF];
    int p = blockIdx.y;
    int base = blockIdx.x * 32;

    for (int i = threadIdx.x; i < 32 * HF; i += 256) {
        int node = base + (i >> 7);
        int c = i & 127;
        float z = 0.f;
        if (node < Nn) {
            float raw = g_out[((size_t)p * Nn + node) * HF + c] + bias[(size_t)p * HF + c];
            z = raw > 0.f ? raw : (__expf(raw) - 1.0f);
        }
        z_sh[i] = z;
    }
    __syncthreads();

    int warpId = threadIdx.x >> 5;
    int lane = threadIdx.x & 31;
    const ulonglong2* W2 = (const ulonglong2*)sem_w1;
    const float4* z4 = (const float4*)z_sh;

    unsigned long long acc[4][2];
    #pragma unroll
    for (int r = 0; r < 4; r++) { acc[r][0] = 0ull; acc[r][1] = 0ull; }

    for (int k4 = 0; k4 < 32; k4++) {
        float4 zv0 = z4[(warpId * 4 + 0) * 32 + k4];
        float4 zv1 = z4[(warpId * 4 + 1) * 32 + k4];
        float4 zv2 = z4[(warpId * 4 + 2) * 32 + k4];
        float4 zv3 = z4[(warpId * 4 + 3) * 32 + k4];
        float z0v[4] = {zv0.x, zv0.y, zv0.z, zv0.w};
        float z1v[4] = {zv1.x, zv1.y, zv1.z, zv1.w};
        float z2v[4] = {zv2.x, zv2.y, zv2.z, zv2.w};
        float z3v[4] = {zv3.x, zv3.y, zv3.z, zv3.w};
        #pragma unroll
        for (int kk = 0; kk < 4; kk++) {
            ulonglong2 wv = W2[(size_t)(k4 * 4 + kk) * 32 + lane];
            unsigned long long p0 = pack2(z0v[kk], z0v[kk]);
            unsigned long long p1 = pack2(z1v[kk], z1v[kk]);
            unsigned long long p2 = pack2(z2v[kk], z2v[kk]);
            unsigned long long p3 = pack2(z3v[kk], z3v[kk]);
            acc[0][0] = fma2(p0, wv.x, acc[0][0]); acc[0][1] = fma2(p0, wv.y, acc[0][1]);
            acc[1][0] = fma2(p1, wv.x, acc[1][0]); acc[1][1] = fma2(p1, wv.y, acc[1][1]);
            acc[2][0] = fma2(p2, wv.x, acc[2][0]); acc[2][1] = fma2(p2, wv.y, acc[2][1]);
            acc[3][0] = fma2(p3, wv.x, acc[3][0]); acc[3][1] = fma2(p3, wv.y, acc[3][1]);
        }
    }

    float4 b14 = ((const float4*)sem_b1)[lane];
    float4 w24 = ((const float4*)sem_w2)[lane];

    float total = 0.f;
    #pragma unroll
    for (int j = 0; j < 4; j++) {
        float4 a;
        unpack2(acc[j][0], a.x, a.y);
        unpack2(acc[j][1], a.z, a.w);
        float cj = tanhf(a.x + b14.x) * w24.x
                 + tanhf(a.y + b14.y) * w24.y
                 + tanhf(a.z + b14.z) * w24.z
                 + tanhf(a.w + b14.w) * w24.w;
        #pragma unroll
        for (int off = 16; off >= 1; off >>= 1)
            cj += __shfl_xor_sync(0xffffffffu, cj, off);
        int node = base + warpId * 4 + j;
        if (node < Nn) total += cj;
    }
    if (lane == 0) atomicAdd(&g_wsum[p], total);
}

// ============================================================
// K6: combine with semantic softmax
// ============================================================
__global__ void final_kernel(const float* __restrict__ bias,
                             float* __restrict__ out) {
    size_t i = (size_t)blockIdx.x * 256 + threadIdx.x;
    if (i >= (size_t)Nn * 32) return;
    float w0 = g_wsum[0] * (1.0f / Nn);
    float w1 = g_wsum[1] * (1.0f / Nn);
    float m = fmaxf(w0, w1);
    float e0 = __expf(w0 - m), e1 = __expf(w1 - m);
    float inv = 1.0f / (e0 + e1);
    float b0 = e0 * inv, b1 = e1 * inv;

    int c4 = (int)(i & 31);
    float4 r0 = ((const float4*)g_out)[i];
    float4 r1 = ((const float4*)g_out)[(size_t)Nn * 32 + i];
    float4 bi0 = ((const float4*)bias)[c4];
    float4 bi1 = ((const float4*)bias)[32 + c4];

    float4 res;
    float v;
    v = r0.x + bi0.x; v = v > 0.f ? v : (__expf(v) - 1.f); res.x = b0 * v;
    v = r0.y + bi0.y; v = v > 0.f ? v : (__expf(v) - 1.f); res.y = b0 * v;
    v = r0.z + bi0.z; v = v > 0.f ? v : (__expf(v) - 1.f); res.z = b0 * v;
    v = r0.w + bi0.w; v = v > 0.f ? v : (__expf(v) - 1.f); res.w = b0 * v;
    v = r1.x + bi1.x; v = v > 0.f ? v : (__expf(v) - 1.f); res.x += b1 * v;
    v = r1.y + bi1.y; v = v > 0.f ? v : (__expf(v) - 1.f); res.y += b1 * v;
    v = r1.z + bi1.z; v = v > 0.f ? v : (__expf(v) - 1.f); res.z += b1 * v;
    v = r1.w + bi1.w; v = v > 0.f ? v : (__expf(v) - 1.f); res.w += b1 * v;

    ((float4*)out)[i] = res;
}

extern "C" void kernel_launch(void* const* d_in, const int* in_sizes, int n_in,
                              void* d_out, int out_size) {
    const float* h      = (const float*)d_in[0];
    const int*   src    = (const int*)  d_in[1];
    const int*   dst    = (const int*)  d_in[2];
    const float* fc_w   = (const float*)d_in[3];
    const float* attn_l = (const float*)d_in[4];
    const float* attn_r = (const float*)d_in[5];
    const float* bias   = (const float*)d_in[6];
    const float* sem_w1 = (const float*)d_in[7];
    const float* sem_b1 = (const float*)d_in[8];
    const float* sem_w2 = (const float*)d_in[9];
    float* out = (float*)d_out;

    void *p_deg, *p_wsum;
    cudaGetSymbolAddress(&p_deg, g_deg);
    cudaGetSymbolAddress(&p_wsum, g_wsum);
    cudaMemsetAsync(p_deg, 0, sizeof(int) * TOT);
    cudaMemsetAsync(p_wsum, 0, sizeof(float) * Pp);

    dim3 gFeat((Nn / 4 + 7) / 8, Pp);
    feat_kernel<<<gFeat, 256>>>(h, fc_w, attn_l, attn_r);

    dim3 gEdge((Ee + 255) / 256, Pp);
    hist_kernel<<<gEdge, 256>>>(dst);
    scan1_kernel<<<SCAN_B, 1024>>>();
    scan23_kernel<<<SCAN_B, 1024>>>();
    scatter_kernel<<<gEdge, 256>>>(src, dst);

    agg_kernel<<<(TOT + 7) / 8, 256>>>();

    dim3 gSem((Nn + 31) / 32, Pp);
    sem_kernel<<<gSem, 256>>>(bias, sem_w1, sem_b1, sem_w2);

    final_kernel<<<((size_t)Nn * 32 + 255) / 256, 256>>>(bias, out);
}

// round 4
// speedup vs baseline: 2.1470x; 1.0282x over previous
#include <cuda_runtime.h>
#include <cuda_bf16.h>
#include <cuda_fp16.h>
#include <math.h>

#define Nn 50000
#define Ee 800000
#define Pp 2
#define Hh 4
#define Ff 32
#define HF 128
#define INF 128
#define TOT (Pp * Nn)          // 100000 destination slots
#define SCAN_B 98              // ceil(TOT/1024)

// ---- scratch (device globals; allocation-free) ----
__device__ __half g_feat_h[(size_t)Pp * Nn * HF]; // 25.6 MB (gather path)
__device__ float g_el[(size_t)Pp * Nn * Hh];
__device__ float g_er[(size_t)Pp * Nn * Hh];
__device__ float g_out[(size_t)Pp * Nn * HF];    // 51.2 MB
__device__ float g_wsum[Pp];
__device__ int   g_deg[TOT];
__device__ int   g_off[TOT];
__device__ int   g_cur[TOT];
__device__ int   g_bsum[SCAN_B];
__device__ int   g_csr_src[(size_t)Pp * Ee];     // 6.4 MB

// ---- packed fp32x2 helpers (Blackwell) ----
__device__ __forceinline__ unsigned long long pack2(float a, float b) {
    unsigned long long r;
    asm("mov.b64 %0, {%1, %2};" : "=l"(r) : "f"(a), "f"(b));
    return r;
}
__device__ __forceinline__ void unpack2(unsigned long long v, float& a, float& b) {
    asm("mov.b64 {%0, %1}, %2;" : "=f"(a), "=f"(b) : "l"(v));
}
__device__ __forceinline__ unsigned long long fma2(unsigned long long a,
                                                   unsigned long long b,
                                                   unsigned long long c) {
    unsigned long long r;
    asm("fma.rn.f32x2 %0, %1, %2, %3;" : "=l"(r) : "l"(a), "l"(b), "l"(c));
    return r;
}

// ============================================================
// K1: feat = h @ W_p (stored fp16) ; el/er attn dots (fp32)
// ============================================================
__global__ void feat_kernel(const float* __restrict__ h,
                            const float* __restrict__ fc_w,
                            const float* __restrict__ attn_l,
                            const float* __restrict__ attn_r) {
    int p = blockIdx.y;
    const ulonglong2* W2 = (const ulonglong2*)(fc_w + (size_t)p * INF * HF);
    int warpId = threadIdx.x >> 5;
    int lane = threadIdx.x & 31;
    int gw = blockIdx.x * 8 + warpId;
    int n0 = gw * 4;                    // Nn % 4 == 0
    if (n0 >= Nn) return;

    const float4* h4 = (const float4*)h;
    const float4* ha = h4 + (size_t)(n0 + 0) * 32;
    const float4* hb = h4 + (size_t)(n0 + 1) * 32;
    const float4* hc = h4 + (size_t)(n0 + 2) * 32;
    const float4* hd = h4 + (size_t)(n0 + 3) * 32;

    unsigned long long acc[4][2];
    #pragma unroll
    for (int r = 0; r < 4; r++) { acc[r][0] = 0ull; acc[r][1] = 0ull; }

    for (int k4 = 0; k4 < 32; k4++) {
        float4 hv0 = __ldg(ha + k4);
        float4 hv1 = __ldg(hb + k4);
        float4 hv2 = __ldg(hc + k4);
        float4 hv3 = __ldg(hd + k4);
        float h0v[4] = {hv0.x, hv0.y, hv0.z, hv0.w};
        float h1v[4] = {hv1.x, hv1.y, hv1.z, hv1.w};
        float h2v[4] = {hv2.x, hv2.y, hv2.z, hv2.w};
        float h3v[4] = {hv3.x, hv3.y, hv3.z, hv3.w};
        #pragma unroll
        for (int kk = 0; kk < 4; kk++) {
            ulonglong2 wv = W2[(size_t)(k4 * 4 + kk) * 32 + lane];
            unsigned long long p0 = pack2(h0v[kk], h0v[kk]);
            unsigned long long p1 = pack2(h1v[kk], h1v[kk]);
            unsigned long long p2 = pack2(h2v[kk], h2v[kk]);
            unsigned long long p3 = pack2(h3v[kk], h3v[kk]);
            acc[0][0] = fma2(p0, wv.x, acc[0][0]); acc[0][1] = fma2(p0, wv.y, acc[0][1]);
            acc[1][0] = fma2(p1, wv.x, acc[1][0]); acc[1][1] = fma2(p1, wv.y, acc[1][1]);
            acc[2][0] = fma2(p2, wv.x, acc[2][0]); acc[2][1] = fma2(p2, wv.y, acc[2][1]);
            acc[3][0] = fma2(p3, wv.x, acc[3][0]); acc[3][1] = fma2(p3, wv.y, acc[3][1]);
        }
    }

    float4 accs[4];
    #pragma unroll
    for (int r = 0; r < 4; r++) {
        unpack2(acc[r][0], accs[r].x, accs[r].y);
        unpack2(acc[r][1], accs[r].z, accs[r].w);
    }

    uint2* feath = (uint2*)g_feat_h;
    #pragma unroll
    for (int r = 0; r < 4; r++) {
        __half2 a01 = __floats2half2_rn(accs[r].x, accs[r].y);
        __half2 a23 = __floats2half2_rn(accs[r].z, accs[r].w);
        uint2 st;
        st.x = *reinterpret_cast<unsigned int*>(&a01);
        st.y = *reinterpret_cast<unsigned int*>(&a23);
        feath[((size_t)p * Nn + n0 + r) * 32 + lane] = st;
    }

    float4 al4 = ((const float4*)(attn_l + (size_t)p * HF))[lane];
    float4 ar4 = ((const float4*)(attn_r + (size_t)p * HF))[lane];
    int head = lane >> 3;

    #pragma unroll
    for (int j = 0; j < 4; j++) {
        float pl = accs[j].x * al4.x + accs[j].y * al4.y + accs[j].z * al4.z + accs[j].w * al4.w;
        float pr = accs[j].x * ar4.x + accs[j].y * ar4.y + accs[j].z * ar4.z + accs[j].w * ar4.w;
        #pragma unroll
        for (int off = 4; off >= 1; off >>= 1) {
            pl += __shfl_xor_sync(0xffffffffu, pl, off);
            pr += __shfl_xor_sync(0xffffffffu, pr, off);
        }
        if ((lane & 7) == 0) {
            g_el[((size_t)p * Nn + n0 + j) * Hh + head] = pl;
            g_er[((size_t)p * Nn + n0 + j) * Hh + head] = pr;
        }
    }
}

// ============================================================
// CSR build: histogram -> scan -> scatter
// ============================================================
__global__ void hist_kernel(const int* __restrict__ dst) {
    int p = blockIdx.y;
    int e = blockIdx.x * 256 + threadIdx.x;
    if (e >= Ee) return;
    atomicAdd(&g_deg[p * Nn + __ldg(dst + (size_t)p * Ee + e)], 1);
}

__global__ void scan1_kernel() {
    __shared__ int wsum[32];
    int tid = threadIdx.x, lane = tid & 31, wid = tid >> 5;
    int i = blockIdx.x * 1024 + tid;
    int v = (i < TOT) ? g_deg[i] : 0;
    int x = v;
    #pragma unroll
    for (int o = 1; o < 32; o <<= 1) {
        int y = __shfl_up_sync(0xffffffffu, x, o);
        if (lane >= o) x += y;
    }
    if (lane == 31) wsum[wid] = x;
    __syncthreads();
    if (wid == 0) {
        int s = wsum[lane];
        #pragma unroll
        for (int o = 1; o < 32; o <<= 1) {
            int y = __shfl_up_sync(0xffffffffu, s, o);
            if (lane >= o) s += y;
        }
        wsum[lane] = s;
    }
    __syncthreads();
    int woff = (wid == 0) ? 0 : wsum[wid - 1];
    if (i < TOT) g_off[i] = woff + x - v;
    if (tid == 1023) g_bsum[blockIdx.x] = wsum[31];
}

__global__ void scan23_kernel() {
    __shared__ int sh_scan[SCAN_B];
    if (threadIdx.x < 32) {
        int lane = threadIdx.x;
        int v[4];
        int s = 0;
        #pragma unroll
        for (int j = 0; j < 4; j++) {
            int idx = lane * 4 + j;
            int t = (idx < SCAN_B) ? g_bsum[idx] : 0;
            v[j] = s;
            s += t;
        }
        int x = s;
        #pragma unroll
        for (int o = 1; o < 32; o <<= 1) {
            int y = __shfl_up_sync(0xffffffffu, x, o);
            if (lane >= o) x += y;
        }
        int excl = x - s;
        #pragma unroll
        for (int j = 0; j < 4; j++) {
            int idx = lane * 4 + j;
            if (idx < SCAN_B) sh_scan[idx] = excl + v[j];
        }
    }
    __syncthreads();
    int i = blockIdx.x * 1024 + threadIdx.x;
    if (i < TOT) {
        int o = g_off[i] + sh_scan[blockIdx.x];
        g_off[i] = o;
        g_cur[i] = o;
    }
}

__global__ void scatter_kernel(const int* __restrict__ src,
                               const int* __restrict__ dst) {
    int p = blockIdx.y;
    int e = blockIdx.x * 256 + threadIdx.x;
    if (e >= Ee) return;
    size_t idx = (size_t)p * Ee + e;
    int d = __ldg(dst + idx);
    int pos = atomicAdd(&g_cur[p * Nn + d], 1);
    g_csr_src[pos] = __ldg(src + idx);
}

// ============================================================
// K4: CSR aggregation — warp per dst node; fp16 feat gather.
// ============================================================
__global__ void agg_kernel() {
    int w = blockIdx.x * 8 + (threadIdx.x >> 5);
    if (w >= TOT) return;
    int lane = threadIdx.x & 31;
    int p = (w >= Nn) ? 1 : 0;
    size_t pbase = (size_t)p * Nn;

    int beg = g_off[w];
    int deg = g_deg[w];
    int head = lane >> 3;
    float erd = g_er[(size_t)w * Hh + head];

    const uint2* feath = (const uint2*)g_feat_h;
    unsigned long long a00 = 0ull, a01 = 0ull;
    unsigned long long a10 = 0ull, a11 = 0ull;
    float den = 0.f;

    for (int j = 0; j < deg; j += 32) {
        int cnt = min(32, deg - j);
        int s = g_csr_src[beg + j + min(lane, cnt - 1)];
        int k = 0;
        for (; k + 4 <= cnt; k += 4) {
            int s0 = __shfl_sync(0xffffffffu, s, k);
            int s1 = __shfl_sync(0xffffffffu, s, k + 1);
            int s2 = __shfl_sync(0xffffffffu, s, k + 2);
            int s3 = __shfl_sync(0xffffffffu, s, k + 3);
            float e0 = g_el[(pbase + s0) * Hh + head];
            float e1 = g_el[(pbase + s1) * Hh + head];
            float e2 = g_el[(pbase + s2) * Hh + head];
            float e3 = g_el[(pbase + s3) * Hh + head];
            uint2 r0 = __ldg(feath + (pbase + s0) * 32 + lane);
            uint2 r1 = __ldg(feath + (pbase + s1) * 32 + lane);
            uint2 r2 = __ldg(feath + (pbase + s2) * 32 + lane);
            uint2 r3 = __ldg(feath + (pbase + s3) * 32 + lane);
            float v0 = e0 + erd; v0 = v0 > 0.f ? v0 : 0.2f * v0;
            float v1 = e1 + erd; v1 = v1 > 0.f ? v1 : 0.2f * v1;
            float v2 = e2 + erd; v2 = v2 > 0.f ? v2 : 0.2f * v2;
            float v3 = e3 + erd; v3 = v3 > 0.f ? v3 : 0.2f * v3;
            float w0 = __expf(v0), w1 = __expf(v1), w2 = __expf(v2), w3 = __expf(v3);

            float2 f0a = __half22float2(*reinterpret_cast<__half2*>(&r0.x));
            float2 f0b = __half22float2(*reinterpret_cast<__half2*>(&r0.y));
            float2 f1a = __half22float2(*reinterpret_cast<__half2*>(&r1.x));
            float2 f1b = __half22float2(*reinterpret_cast<__half2*>(&r1.y));
            float2 f2a = __half22float2(*reinterpret_cast<__half2*>(&r2.x));
            float2 f2b = __half22float2(*reinterpret_cast<__half2*>(&r2.y));
            float2 f3a = __half22float2(*reinterpret_cast<__half2*>(&r3.x));
            float2 f3b = __half22float2(*reinterpret_cast<__half2*>(&r3.y));

            unsigned long long p0 = pack2(w0, w0);
            unsigned long long p1 = pack2(w1, w1);
            unsigned long long p2 = pack2(w2, w2);
            unsigned long long p3 = pack2(w3, w3);
            a00 = fma2(p0, pack2(f0a.x, f0a.y), a00);
            a01 = fma2(p0, pack2(f0b.x, f0b.y), a01);
            a10 = fma2(p1, pack2(f1a.x, f1a.y), a10);
            a11 = fma2(p1, pack2(f1b.x, f1b.y), a11);
            a00 = fma2(p2, pack2(f2a.x, f2a.y), a00);
            a01 = fma2(p2, pack2(f2b.x, f2b.y), a01);
            a10 = fma2(p3, pack2(f3a.x, f3a.y), a10);
            a11 = fma2(p3, pack2(f3b.x, f3b.y), a11);
            den += (w0 + w1) + (w2 + w3);
        }
        for (; k < cnt; k++) {
            int s0 = __shfl_sync(0xffffffffu, s, k);
            float e0 = g_el[(pbase + s0) * Hh + head];
            uint2 r0 = __ldg(feath + (pbase + s0) * 32 + lane);
            float v0 = e0 + erd; v0 = v0 > 0.f ? v0 : 0.2f * v0;
            float w0 = __expf(v0);
            float2 f0a = __half22float2(*reinterpret_cast<__half2*>(&r0.x));
            float2 f0b = __half22float2(*reinterpret_cast<__half2*>(&r0.y));
            unsigned long long p0 = pack2(w0, w0);
            a00 = fma2(p0, pack2(f0a.x, f0a.y), a00);
            a01 = fma2(p0, pack2(f0b.x, f0b.y), a01);
            den += w0;
        }
    }

    float ax0, ay0, az0, aw0, ax1, ay1, az1, aw1;
    unpack2(a00, ax0, ay0); unpack2(a01, az0, aw0);
    unpack2(a10, ax1, ay1); unpack2(a11, az1, aw1);
    float inv = 1.0f / fmaxf(den, 1e-9f);
    float4 r;
    r.x = (ax0 + ax1) * inv;
    r.y = (ay0 + ay1) * inv;
    r.z = (az0 + az1) * inv;
    r.w = (aw0 + aw1) * inv;
    ((float4*)g_out)[(size_t)w * 32 + lane] = r;
}

// ============================================================
// K5: semantic attention scores (packed f32x2 GEMM)
// ============================================================
__global__ void sem_kernel(const float* __restrict__ bias,
                           const float* __restrict__ sem_w1,
                           const float* __restrict__ sem_b1,
                           const float* __restrict__ sem_w2) {
    __shared__ __align__(16) float z_sh[32 * HF];
    int p = blockIdx.y;
    int base = blockIdx.x * 32;

    for (int i = threadIdx.x; i < 32 * HF; i += 256) {
        int node = base + (i >> 7);
        int c = i & 127;
        float z = 0.f;
        if (node < Nn) {
            float raw = g_out[((size_t)p * Nn + node) * HF + c] + bias[(size_t)p * HF + c];
            z = raw > 0.f ? raw : (__expf(raw) - 1.0f);
        }
        z_sh[i] = z;
    }
    __syncthreads();

    int warpId = threadIdx.x >> 5;
    int lane = threadIdx.x & 31;
    const ulonglong2* W2 = (const ulonglong2*)sem_w1;
    const float4* z4 = (const float4*)z_sh;

    unsigned long long acc[4][2];
    #pragma unroll
    for (int r = 0; r < 4; r++) { acc[r][0] = 0ull; acc[r][1] = 0ull; }

    for (int k4 = 0; k4 < 32; k4++) {
        float4 zv0 = z4[(warpId * 4 + 0) * 32 + k4];
        float4 zv1 = z4[(warpId * 4 + 1) * 32 + k4];
        float4 zv2 = z4[(warpId * 4 + 2) * 32 + k4];
        float4 zv3 = z4[(warpId * 4 + 3) * 32 + k4];
        float z0v[4] = {zv0.x, zv0.y, zv0.z, zv0.w};
        float z1v[4] = {zv1.x, zv1.y, zv1.z, zv1.w};
        float z2v[4] = {zv2.x, zv2.y, zv2.z, zv2.w};
        float z3v[4] = {zv3.x, zv3.y, zv3.z, zv3.w};
        #pragma unroll
        for (int kk = 0; kk < 4; kk++) {
            ulonglong2 wv = W2[(size_t)(k4 * 4 + kk) * 32 + lane];
            unsigned long long p0 = pack2(z0v[kk], z0v[kk]);
            unsigned long long p1 = pack2(z1v[kk], z1v[kk]);
            unsigned long long p2 = pack2(z2v[kk], z2v[kk]);
            unsigned long long p3 = pack2(z3v[kk], z3v[kk]);
            acc[0][0] = fma2(p0, wv.x, acc[0][0]); acc[0][1] = fma2(p0, wv.y, acc[0][1]);
            acc[1][0] = fma2(p1, wv.x, acc[1][0]); acc[1][1] = fma2(p1, wv.y, acc[1][1]);
            acc[2][0] = fma2(p2, wv.x, acc[2][0]); acc[2][1] = fma2(p2, wv.y, acc[2][1]);
            acc[3][0] = fma2(p3, wv.x, acc[3][0]); acc[3][1] = fma2(p3, wv.y, acc[3][1]);
        }
    }

    float4 b14 = ((const float4*)sem_b1)[lane];
    float4 w24 = ((const float4*)sem_w2)[lane];

    float total = 0.f;
    #pragma unroll
    for (int j = 0; j < 4; j++) {
        float4 a;
        unpack2(acc[j][0], a.x, a.y);
        unpack2(acc[j][1], a.z, a.w);
        float cj = tanhf(a.x + b14.x) * w24.x
                 + tanhf(a.y + b14.y) * w24.y
                 + tanhf(a.z + b14.z) * w24.z
                 + tanhf(a.w + b14.w) * w24.w;
        #pragma unroll
        for (int off = 16; off >= 1; off >>= 1)
            cj += __shfl_xor_sync(0xffffffffu, cj, off);
        int node = base + warpId * 4 + j;
        if (node < Nn) total += cj;
    }
    if (lane == 0) atomicAdd(&g_wsum[p], total);
}

// ============================================================
// K6: combine with semantic softmax
// ============================================================
__global__ void final_kernel(const float* __restrict__ bias,
                             float* __restrict__ out) {
    size_t i = (size_t)blockIdx.x * 256 + threadIdx.x;
    if (i >= (size_t)Nn * 32) return;
    float w0 = g_wsum[0] * (1.0f / Nn);
    float w1 = g_wsum[1] * (1.0f / Nn);
    float m = fmaxf(w0, w1);
    float e0 = __expf(w0 - m), e1 = __expf(w1 - m);
    float inv = 1.0f / (e0 + e1);
    float b0 = e0 * inv, b1 = e1 * inv;

    int c4 = (int)(i & 31);
    float4 r0 = ((const float4*)g_out)[i];
    float4 r1 = ((const float4*)g_out)[(size_t)Nn * 32 + i];
    float4 bi0 = ((const float4*)bias)[c4];
    float4 bi1 = ((const float4*)bias)[32 + c4];

    float4 res;
    float v;
    v = r0.x + bi0.x; v = v > 0.f ? v : (__expf(v) - 1.f); res.x = b0 * v;
    v = r0.y + bi0.y; v = v > 0.f ? v : (__expf(v) - 1.f); res.y = b0 * v;
    v = r0.z + bi0.z; v = v > 0.f ? v : (__expf(v) - 1.f); res.z = b0 * v;
    v = r0.w + bi0.w; v = v > 0.f ? v : (__expf(v) - 1.f); res.w = b0 * v;
    v = r1.x + bi1.x; v = v > 0.f ? v : (__expf(v) - 1.f); res.x += b1 * v;
    v = r1.y + bi1.y; v = v > 0.f ? v : (__expf(v) - 1.f); res.y += b1 * v;
    v = r1.z + bi1.z; v = v > 0.f ? v : (__expf(v) - 1.f); res.z += b1 * v;
    v = r1.w + bi1.w; v = v > 0.f ? v : (__expf(v) - 1.f); res.w += b1 * v;

    ((float4*)out)[i] = res;
}

extern "C" void kernel_launch(void* const* d_in, const int* in_sizes, int n_in,
                              void* d_out, int out_size) {
    const float* h      = (const float*)d_in[0];
    const int*   src    = (const int*)  d_in[1];
    const int*   dst    = (const int*)  d_in[2];
    const float* fc_w   = (const float*)d_in[3];
    const float* attn_l = (const float*)d_in[4];
    const float* attn_r = (const float*)d_in[5];
    const float* bias   = (const float*)d_in[6];
    const float* sem_w1 = (const float*)d_in[7];
    const float* sem_b1 = (const float*)d_in[8];
    const float* sem_w2 = (const float*)d_in[9];
    float* out = (float*)d_out;

    // side stream + events for the forked CSR-build branch
    // (created once, outside graph capture — first call is the
    //  uncaptured correctness run)
    static cudaStream_t s2 = nullptr;
    static cudaEvent_t evFork = nullptr, evJoin = nullptr;
    if (s2 == nullptr) {
        cudaStreamCreateWithFlags(&s2, cudaStreamNonBlocking);
        cudaEventCreateWithFlags(&evFork, cudaEventDisableTiming);
        cudaEventCreateWithFlags(&evJoin, cudaEventDisableTiming);
    }

    void *p_deg, *p_wsum;
    cudaGetSymbolAddress(&p_deg, g_deg);
    cudaGetSymbolAddress(&p_wsum, g_wsum);

    // fork: CSR build on s2, feat GEMM on main stream
    cudaEventRecord(evFork, 0);
    cudaStreamWaitEvent(s2, evFork, 0);

    // --- branch B (s2): CSR build ---
    cudaMemsetAsync(p_deg, 0, sizeof(int) * TOT, s2);
    dim3 gEdge((Ee + 255) / 256, Pp);
    hist_kernel<<<gEdge, 256, 0, s2>>>(dst);
    scan1_kernel<<<SCAN_B, 1024, 0, s2>>>();
    scan23_kernel<<<SCAN_B, 1024, 0, s2>>>();
    scatter_kernel<<<gEdge, 256, 0, s2>>>(src, dst);
    cudaEventRecord(evJoin, s2);

    // --- branch A (main): features + attn dots ---
    cudaMemsetAsync(p_wsum, 0, sizeof(float) * Pp);
    dim3 gFeat((Nn / 4 + 7) / 8, Pp);
    feat_kernel<<<gFeat, 256>>>(h, fc_w, attn_l, attn_r);

    // join
    cudaStreamWaitEvent(0, evJoin, 0);

    agg_kernel<<<(TOT + 7) / 8, 256>>>();

    dim3 gSem((Nn + 31) / 32, Pp);
    sem_kernel<<<gSem, 256>>>(bias, sem_w1, sem_b1, sem_w2);

    final_kernel<<<((size_t)Nn * 32 + 255) / 256, 256>>>(bias, out);
}